// round 1
// baseline (speedup 1.0000x reference)
#include <cuda_runtime.h>
#include <cstddef>

// Problem constants
#define BB 64
#define TT 2048
#define FF 128
#define UU 128
#define GG 512               // 4*U
#define MM (BB * TT)         // 131072 rows of x

// Scratch: precomputed z = x @ W_x + b, for both directions.
// [dir][b*T + t][512]  -> 2 * 131072 * 512 floats = 512 MB (static device array)
__device__ float g_Z[2ull * 131072ull * 512ull];

// ---------------- f32x2 packed helpers (sm_100+) ----------------
__device__ __forceinline__ unsigned long long fma2(unsigned long long a,
                                                   unsigned long long b,
                                                   unsigned long long c) {
    unsigned long long d;
    asm("fma.rn.f32x2 %0, %1, %2, %3;" : "=l"(d) : "l"(a), "l"(b), "l"(c));
    return d;
}
__device__ __forceinline__ unsigned long long pk(float x, float y) {
    unsigned long long d;
    asm("mov.b64 %0, {%1, %2};" : "=l"(d) : "f"(x), "f"(y));
    return d;
}
__device__ __forceinline__ float2 upk(unsigned long long a) {
    float2 r;
    asm("mov.b64 {%0, %1}, %2;" : "=f"(r.x), "=f"(r.y) : "l"(a));
    return r;
}

// ---------------- activations ----------------
__device__ __forceinline__ float sigm(float x) {
    return __fdividef(1.0f, 1.0f + __expf(-x));
}
__device__ __forceinline__ float tanh_fast(float x) {
    float ax = fabsf(x);
    float e  = __expf(-2.0f * ax);
    float r  = __fdividef(1.0f - e, 1.0f + e);
    return copysignf(r, x);
}

// =====================================================================
// Phase 1: Z[dir] = X @ W_x(dir) + bias(dir)
// Classic 128x128 block / 8x8 thread tile SGEMM with f32x2 FMAs. K=128.
// grid = (4, 1024, 2), block = 256
// =====================================================================
__global__ __launch_bounds__(256, 2) void gemm_xw(
    const float* __restrict__ A,     // x  [131072, 128]
    const float* __restrict__ Wfw,   // [256, 512]
    const float* __restrict__ bfw,   // [512]
    const float* __restrict__ Wbw,
    const float* __restrict__ bbw) {
    const int dir = blockIdx.z;
    const float* Bw   = dir ? Wbw : Wfw;   // use rows 0..127 (W_x part)
    const float* bias = dir ? bbw : bfw;
    float* C = g_Z + (size_t)dir * ((size_t)MM * GG);

    const int n0 = blockIdx.x * 128;
    const int m0 = blockIdx.y * 128;

    __shared__ float As[16][128];   // [k][m]
    __shared__ float Bs[16][128];   // [k][n]

    const int tid = threadIdx.x;
    const int tx = tid & 15, ty = tid >> 4;

    // load-index precompute (2 float4 per thread per matrix)
    const int qa0 = tid, qa1 = tid + 256;
    const int am0 = qa0 >> 2, ak0 = (qa0 & 3) * 4;
    const int am1 = qa1 >> 2, ak1 = (qa1 & 3) * 4;
    const int bk0 = qa0 >> 5, bn0 = (qa0 & 31) * 4;
    const int bk1 = qa1 >> 5, bn1 = (qa1 & 31) * 4;

    float4 ra0, ra1, rb0, rb1;

    unsigned long long acc[8][4];
#pragma unroll
    for (int m = 0; m < 8; m++)
#pragma unroll
        for (int n = 0; n < 4; n++) acc[m][n] = 0ull;

    // prologue load k-tile 0
    {
        const int k0 = 0;
        ra0 = *(const float4*)(A + (size_t)(m0 + am0) * FF + k0 + ak0);
        ra1 = *(const float4*)(A + (size_t)(m0 + am1) * FF + k0 + ak1);
        rb0 = *(const float4*)(Bw + (size_t)(k0 + bk0) * GG + n0 + bn0);
        rb1 = *(const float4*)(Bw + (size_t)(k0 + bk1) * GG + n0 + bn1);
        As[ak0 + 0][am0] = ra0.x; As[ak0 + 1][am0] = ra0.y;
        As[ak0 + 2][am0] = ra0.z; As[ak0 + 3][am0] = ra0.w;
        As[ak1 + 0][am1] = ra1.x; As[ak1 + 1][am1] = ra1.y;
        As[ak1 + 2][am1] = ra1.z; As[ak1 + 3][am1] = ra1.w;
        *(float4*)&Bs[bk0][bn0] = rb0;
        *(float4*)&Bs[bk1][bn1] = rb1;
    }
    __syncthreads();

    for (int kt = 0; kt < 8; kt++) {
        if (kt < 7) {
            const int k0 = (kt + 1) * 16;
            ra0 = *(const float4*)(A + (size_t)(m0 + am0) * FF + k0 + ak0);
            ra1 = *(const float4*)(A + (size_t)(m0 + am1) * FF + k0 + ak1);
            rb0 = *(const float4*)(Bw + (size_t)(k0 + bk0) * GG + n0 + bn0);
            rb1 = *(const float4*)(Bw + (size_t)(k0 + bk1) * GG + n0 + bn1);
        }
#pragma unroll
        for (int kk = 0; kk < 16; kk++) {
            float4 a0 = *(const float4*)&As[kk][ty * 8];
            float4 a1 = *(const float4*)&As[kk][ty * 8 + 4];
            ulonglong2 b0 = *(const ulonglong2*)&Bs[kk][tx * 8];
            ulonglong2 b1 = *(const ulonglong2*)&Bs[kk][tx * 8 + 4];
            float av[8] = {a0.x, a0.y, a0.z, a0.w, a1.x, a1.y, a1.z, a1.w};
            unsigned long long bv[4] = {b0.x, b0.y, b1.x, b1.y};
#pragma unroll
            for (int m = 0; m < 8; m++) {
                unsigned long long am = pk(av[m], av[m]);
#pragma unroll
                for (int n = 0; n < 4; n++) acc[m][n] = fma2(am, bv[n], acc[m][n]);
            }
        }
        __syncthreads();
        if (kt < 7) {
            As[ak0 + 0][am0] = ra0.x; As[ak0 + 1][am0] = ra0.y;
            As[ak0 + 2][am0] = ra0.z; As[ak0 + 3][am0] = ra0.w;
            As[ak1 + 0][am1] = ra1.x; As[ak1 + 1][am1] = ra1.y;
            As[ak1 + 2][am1] = ra1.z; As[ak1 + 3][am1] = ra1.w;
            *(float4*)&Bs[bk0][bn0] = rb0;
            *(float4*)&Bs[bk1][bn1] = rb1;
            __syncthreads();
        }
    }

    float bl[8];
#pragma unroll
    for (int i = 0; i < 8; i++) bl[i] = bias[n0 + tx * 8 + i];
#pragma unroll
    for (int m = 0; m < 8; m++) {
        float2 p0 = upk(acc[m][0]), p1 = upk(acc[m][1]);
        float2 p2 = upk(acc[m][2]), p3 = upk(acc[m][3]);
        float4 c0 = make_float4(p0.x + bl[0], p0.y + bl[1], p1.x + bl[2], p1.y + bl[3]);
        float4 c1 = make_float4(p2.x + bl[4], p2.y + bl[5], p3.x + bl[6], p3.y + bl[7]);
        float* cp = C + (size_t)(m0 + ty * 8 + m) * GG + n0 + tx * 8;
        *(float4*)cp = c0;
        *(float4*)(cp + 4) = c1;
    }
}

// =====================================================================
// Phase 2: persistent recurrence. 1 CTA per (batch, direction).
// 512 threads, thread j owns gate-column j of W_h:
//   rows 0..91  -> 46 packed f32x2 register pairs
//   rows 92..127-> 18 packed pairs in shared memory (73.7 KB)
// grid = 128, block = 512, dynSmem = 76800
// =====================================================================
__global__ __launch_bounds__(512) void lstm_rec(
    const float* __restrict__ Wfw,
    const float* __restrict__ Wbw,
    float* __restrict__ out) {
    const int j   = threadIdx.x;         // gate column 0..511
    const int dir = blockIdx.x & 1;
    const int b   = blockIdx.x >> 1;
    const float* W  = dir ? Wbw : Wfw;
    const float* Wh = W + FF * GG;       // rows 128..255 = W_h

    extern __shared__ unsigned char sraw[];
    unsigned long long* ws2 = (unsigned long long*)sraw;          // 18*512 ull = 73728 B
    float* zs   = (float*)(sraw + 18 * 512 * 8);                  // 512 floats
    float* hbuf = (float*)(sraw + 18 * 512 * 8 + 512 * 4);        // 128 floats (16B aligned)

    // Load weight column: register part (rows 0..91 as 46 pairs)
    unsigned long long wreg[46];
#pragma unroll
    for (int k = 0; k < 46; k++)
        wreg[k] = pk(Wh[(size_t)(2 * k) * GG + j], Wh[(size_t)(2 * k + 1) * GG + j]);
    // smem part (rows 92..127 as 18 pairs)
#pragma unroll
    for (int q = 0; q < 18; q++)
        ws2[q * 512 + j] = pk(Wh[(size_t)(92 + 2 * q) * GG + j],
                              Wh[(size_t)(93 + 2 * q) * GG + j]);
    if (j < UU) hbuf[j] = 0.0f;
    float c = 0.0f;
    const int g = j >> 7;  // 0:i 1:j 2:f 3:o  (uniform per warp)
    __syncthreads();

    // z-prefetch pointer (forward walks up, backward walks down)
    const size_t base = ((size_t)dir * MM + (size_t)b * TT) * GG;
    const float* zp;
    long long zstep;
    int tt0;
    if (dir == 0) { zp = g_Z + base + j;                          zstep =  GG; tt0 = 0; }
    else          { zp = g_Z + base + (size_t)(TT - 1) * GG + j;  zstep = -GG; tt0 = TT - 1; }
    float znext = *zp;

    float* outp = out + ((size_t)b * TT + tt0) * (2 * UU) + dir * UU + j;  // valid iff j<128
    const long long ostep = (dir == 0) ? (2 * UU) : -(2 * UU);

    for (int t = 0; t < TT; t++) {
        float zc = znext;
        if (t + 1 < TT) { zp += zstep; znext = *zp; }  // prefetch next step

        unsigned long long acc0 = 0ull, acc1 = 0ull;
        const ulonglong2* hb = (const ulonglong2*)hbuf;  // 32 x (pair of f32x2)
#pragma unroll
        for (int p = 0; p < 23; p++) {                   // rows 0..91 (registers)
            ulonglong2 h2 = hb[p];
            acc0 = fma2(wreg[2 * p], h2.x, acc0);
            acc1 = fma2(wreg[2 * p + 1], h2.y, acc1);
        }
#pragma unroll
        for (int q = 0; q < 9; q++) {                    // rows 92..127 (smem)
            ulonglong2 h2 = hb[23 + q];
            acc0 = fma2(ws2[(2 * q) * 512 + j], h2.x, acc0);
            acc1 = fma2(ws2[(2 * q + 1) * 512 + j], h2.y, acc1);
        }
        float2 s0 = upk(acc0), s1 = upk(acc1);
        float z = (s0.x + s0.y) + (s1.x + s1.y) + zc;

        float act;
        if (g == 1) {
            act = tanh_fast(z);
        } else {
            if (g == 2) z += 1.0f;   // forget bias
            act = sigm(z);
        }
        zs[j] = act;
        __syncthreads();

        if (j < UU) {
            float ai = zs[j], aj = zs[j + 128], af = zs[j + 256], ao = zs[j + 384];
            c = fmaf(c, af, ai * aj);
            float h = ao * tanh_fast(c);
            hbuf[j] = h;
            *outp = h;
            outp += ostep;
        }
        __syncthreads();
    }
}

extern "C" void kernel_launch(void* const* d_in, const int* in_sizes, int n_in,
                              void* d_out, int out_size) {
    const float* x   = (const float*)d_in[0];
    const float* Wfw = (const float*)d_in[1];
    const float* bfw = (const float*)d_in[2];
    const float* Wbw = (const float*)d_in[3];
    const float* bbw = (const float*)d_in[4];
    float* out = (float*)d_out;

    cudaFuncSetAttribute(lstm_rec, cudaFuncAttributeMaxDynamicSharedMemorySize, 76800);

    dim3 gg(4, 1024, 2);
    gemm_xw<<<gg, 256>>>(x, Wfw, bfw, Wbw, bbw);
    lstm_rec<<<128, 512, 76800>>>(Wfw, Wbw, out);
}

// round 2
// speedup vs baseline: 1.1438x; 1.1438x over previous
#include <cuda_runtime.h>
#include <cstddef>

// Problem constants
#define BB 64
#define TT 2048
#define FF 128
#define UU 128
#define GG 512               // 4*U
#define MM (BB * TT)         // 131072 rows of x

// Scratch: precomputed z = x @ W_x + b, for both directions.
__device__ float g_Z[2ull * 131072ull * 512ull];

// ---------------- f32x2 packed helpers (sm_100+) ----------------
__device__ __forceinline__ unsigned long long fma2(unsigned long long a,
                                                   unsigned long long b,
                                                   unsigned long long c) {
    unsigned long long d;
    asm("fma.rn.f32x2 %0, %1, %2, %3;" : "=l"(d) : "l"(a), "l"(b), "l"(c));
    return d;
}
__device__ __forceinline__ unsigned long long pk(float x, float y) {
    unsigned long long d;
    asm("mov.b64 %0, {%1, %2};" : "=l"(d) : "f"(x), "f"(y));
    return d;
}
__device__ __forceinline__ float2 upk(unsigned long long a) {
    float2 r;
    asm("mov.b64 {%0, %1}, %2;" : "=f"(r.x), "=f"(r.y) : "l"(a));
    return r;
}

// ---------------- activations ----------------
__device__ __forceinline__ float sigm(float x) {
    return __fdividef(1.0f, 1.0f + __expf(-x));
}
__device__ __forceinline__ float tanh_fast(float x) {
    float ax = fabsf(x);
    float e  = __expf(-2.0f * ax);
    float r  = __fdividef(1.0f - e, 1.0f + e);
    return copysignf(r, x);
}

// =====================================================================
// Phase 1: Z[dir] = X @ W_x(dir) + bias(dir)
// 128x128 block / 8x8 thread tile SGEMM, f32x2 FMAs, A pre-packed in smem.
// grid = (4, 1024, 2), block = 256
// =====================================================================
__global__ __launch_bounds__(256, 2) void gemm_xw(
    const float* __restrict__ A,     // x  [131072, 128]
    const float* __restrict__ Wfw,   // [256, 512]
    const float* __restrict__ bfw,   // [512]
    const float* __restrict__ Wbw,
    const float* __restrict__ bbw) {
    const int dir = blockIdx.z;
    const float* Bw   = dir ? Wbw : Wfw;   // rows 0..127 = W_x part
    const float* bias = dir ? bbw : bfw;
    float* C = g_Z + (size_t)dir * ((size_t)MM * GG);

    const int n0 = blockIdx.x * 128;
    const int m0 = blockIdx.y * 128;

    __shared__ unsigned long long As2[16][128];  // [k][m], {a,a} packed (16 KB)
    __shared__ float Bs[16][128];                // [k][n] (8 KB)

    const int tid = threadIdx.x;
    const int tx = tid & 15, ty = tid >> 4;

    const int qa0 = tid, qa1 = tid + 256;
    const int am0 = qa0 >> 2, ak0 = (qa0 & 3) * 4;
    const int am1 = qa1 >> 2, ak1 = (qa1 & 3) * 4;
    const int bk0 = qa0 >> 5, bn0 = (qa0 & 31) * 4;
    const int bk1 = qa1 >> 5, bn1 = (qa1 & 31) * 4;

    float4 ra0, ra1, rb0, rb1;

    unsigned long long acc[8][4];
#pragma unroll
    for (int m = 0; m < 8; m++)
#pragma unroll
        for (int n = 0; n < 4; n++) acc[m][n] = 0ull;

    // prologue load k-tile 0
    {
        const int k0 = 0;
        ra0 = *(const float4*)(A + (size_t)(m0 + am0) * FF + k0 + ak0);
        ra1 = *(const float4*)(A + (size_t)(m0 + am1) * FF + k0 + ak1);
        rb0 = *(const float4*)(Bw + (size_t)(k0 + bk0) * GG + n0 + bn0);
        rb1 = *(const float4*)(Bw + (size_t)(k0 + bk1) * GG + n0 + bn1);
        As2[ak0 + 0][am0] = pk(ra0.x, ra0.x); As2[ak0 + 1][am0] = pk(ra0.y, ra0.y);
        As2[ak0 + 2][am0] = pk(ra0.z, ra0.z); As2[ak0 + 3][am0] = pk(ra0.w, ra0.w);
        As2[ak1 + 0][am1] = pk(ra1.x, ra1.x); As2[ak1 + 1][am1] = pk(ra1.y, ra1.y);
        As2[ak1 + 2][am1] = pk(ra1.z, ra1.z); As2[ak1 + 3][am1] = pk(ra1.w, ra1.w);
        *(float4*)&Bs[bk0][bn0] = rb0;
        *(float4*)&Bs[bk1][bn1] = rb1;
    }
    __syncthreads();

    for (int kt = 0; kt < 8; kt++) {
        if (kt < 7) {
            const int k0 = (kt + 1) * 16;
            ra0 = *(const float4*)(A + (size_t)(m0 + am0) * FF + k0 + ak0);
            ra1 = *(const float4*)(A + (size_t)(m0 + am1) * FF + k0 + ak1);
            rb0 = *(const float4*)(Bw + (size_t)(k0 + bk0) * GG + n0 + bn0);
            rb1 = *(const float4*)(Bw + (size_t)(k0 + bk1) * GG + n0 + bn1);
        }
#pragma unroll
        for (int kk = 0; kk < 16; kk++) {
            const unsigned long long* ar = &As2[kk][ty * 8];
            ulonglong2 a01 = *(const ulonglong2*)(ar + 0);
            ulonglong2 a23 = *(const ulonglong2*)(ar + 2);
            ulonglong2 a45 = *(const ulonglong2*)(ar + 4);
            ulonglong2 a67 = *(const ulonglong2*)(ar + 6);
            ulonglong2 b0 = *(const ulonglong2*)&Bs[kk][tx * 8];
            ulonglong2 b1 = *(const ulonglong2*)&Bs[kk][tx * 8 + 4];
            unsigned long long av[8] = {a01.x, a01.y, a23.x, a23.y,
                                        a45.x, a45.y, a67.x, a67.y};
            unsigned long long bv[4] = {b0.x, b0.y, b1.x, b1.y};
#pragma unroll
            for (int m = 0; m < 8; m++)
#pragma unroll
                for (int n = 0; n < 4; n++) acc[m][n] = fma2(av[m], bv[n], acc[m][n]);
        }
        __syncthreads();
        if (kt < 7) {
            As2[ak0 + 0][am0] = pk(ra0.x, ra0.x); As2[ak0 + 1][am0] = pk(ra0.y, ra0.y);
            As2[ak0 + 2][am0] = pk(ra0.z, ra0.z); As2[ak0 + 3][am0] = pk(ra0.w, ra0.w);
            As2[ak1 + 0][am1] = pk(ra1.x, ra1.x); As2[ak1 + 1][am1] = pk(ra1.y, ra1.y);
            As2[ak1 + 2][am1] = pk(ra1.z, ra1.z); As2[ak1 + 3][am1] = pk(ra1.w, ra1.w);
            *(float4*)&Bs[bk0][bn0] = rb0;
            *(float4*)&Bs[bk1][bn1] = rb1;
            __syncthreads();
        }
    }

    float bl[8];
#pragma unroll
    for (int i = 0; i < 8; i++) bl[i] = bias[n0 + tx * 8 + i];
#pragma unroll
    for (int m = 0; m < 8; m++) {
        float2 p0 = upk(acc[m][0]), p1 = upk(acc[m][1]);
        float2 p2 = upk(acc[m][2]), p3 = upk(acc[m][3]);
        float4 c0 = make_float4(p0.x + bl[0], p0.y + bl[1], p1.x + bl[2], p1.y + bl[3]);
        float4 c1 = make_float4(p2.x + bl[4], p2.y + bl[5], p3.x + bl[6], p3.y + bl[7]);
        float* cp = C + (size_t)(m0 + ty * 8 + m) * GG + n0 + tx * 8;
        *(float4*)cp = c0;
        *(float4*)(cp + 4) = c1;
    }
}

// =====================================================================
// Phase 2: persistent recurrence. 1 CTA per (batch, direction).
// 256 threads, thread t owns gate-columns t and t+256:
//   rows 0..99   -> 50 packed f32x2 register pairs per column (200 regs)
//   rows 100..127-> 14 pairs per column in smem as ulonglong2 blocks
// grid = 128, block = 256
// =====================================================================
#define RECTHR 256
#define SMBLK  7          // ulonglong2 blocks (2 pairs = 4 rows each): rows 100..127
#define RPAIR  50         // register pairs per column (rows 0..99)

__global__ __launch_bounds__(RECTHR) void lstm_rec(
    const float* __restrict__ Wfw,
    const float* __restrict__ Wbw,
    float* __restrict__ out) {
    const int tid = threadIdx.x;
    const int j0  = tid;             // gate column A
    const int j1  = tid + 256;       // gate column B
    const int dir = blockIdx.x & 1;
    const int b   = blockIdx.x >> 1;
    const float* W  = dir ? Wbw : Wfw;
    const float* Wh = W + FF * GG;   // rows 128..255 = W_h

    extern __shared__ unsigned char sraw[];
    // ws[q][col] : ulonglong2 = pairs (50+2q, 51+2q) i.e. rows 100+4q..103+4q
    ulonglong2* ws = (ulonglong2*)sraw;                         // 7*512*16 = 57344 B
    float* zs   = (float*)(sraw + SMBLK * 512 * 16);            // 512 floats
    float* hbuf = (float*)(sraw + SMBLK * 512 * 16 + 2048);     // 128 floats, 16B aligned

    // ---- load weights ----
    unsigned long long w0[2 * RPAIR];   // column j0: pairs 0..49
    unsigned long long w1[2 * RPAIR];   // column j1
#pragma unroll
    for (int p = 0; p < RPAIR; p++) {
        w0[p] = pk(Wh[(size_t)(2 * p) * GG + j0], Wh[(size_t)(2 * p + 1) * GG + j0]);
        w1[p] = pk(Wh[(size_t)(2 * p) * GG + j1], Wh[(size_t)(2 * p + 1) * GG + j1]);
    }
#pragma unroll
    for (int q = 0; q < SMBLK; q++) {
        int r = 100 + 4 * q;
        ulonglong2 vA, vB;
        vA.x = pk(Wh[(size_t)(r + 0) * GG + j0], Wh[(size_t)(r + 1) * GG + j0]);
        vA.y = pk(Wh[(size_t)(r + 2) * GG + j0], Wh[(size_t)(r + 3) * GG + j0]);
        vB.x = pk(Wh[(size_t)(r + 0) * GG + j1], Wh[(size_t)(r + 1) * GG + j1]);
        vB.y = pk(Wh[(size_t)(r + 2) * GG + j1], Wh[(size_t)(r + 3) * GG + j1]);
        ws[q * 512 + j0] = vA;
        ws[q * 512 + j1] = vB;
    }
    if (tid < UU) hbuf[tid] = 0.0f;
    float c = 0.0f;
    __syncthreads();

    // ---- z stream (prefetch one step ahead) ----
    const size_t base = ((size_t)dir * MM + (size_t)b * TT) * GG;
    const float* zp;
    long long zstep;
    int tt0;
    if (dir == 0) { zp = g_Z + base;                          zstep =  GG; tt0 = 0; }
    else          { zp = g_Z + base + (size_t)(TT - 1) * GG;  zstep = -GG; tt0 = TT - 1; }
    float zn0 = zp[j0], zn1 = zp[j1];

    float* outp = out + ((size_t)b * TT + tt0) * (2 * UU) + dir * UU + tid; // valid iff tid<128
    const long long ostep = (dir == 0) ? (2 * UU) : -(2 * UU);
    const int q4 = tid & 127;

    for (int t = 0; t < TT; t++) {
        float zc0 = zn0, zc1 = zn1;
        if (t + 1 < TT) { zp += zstep; zn0 = zp[j0]; zn1 = zp[j1]; }

        const ulonglong2* hb = (const ulonglong2*)hbuf;  // hb[p] = h pairs (2p, 2p+1)
        unsigned long long a00 = 0ull, a01 = 0ull, a10 = 0ull, a11 = 0ull;
#pragma unroll
        for (int p = 0; p < 25; p++) {                   // rows 0..99 (registers)
            ulonglong2 h2 = hb[p];
            a00 = fma2(w0[2 * p], h2.x, a00);
            a01 = fma2(w0[2 * p + 1], h2.y, a01);
            a10 = fma2(w1[2 * p], h2.x, a10);
            a11 = fma2(w1[2 * p + 1], h2.y, a11);
        }
#pragma unroll
        for (int qq = 0; qq < SMBLK; qq++) {             // rows 100..127 (smem)
            ulonglong2 h2 = hb[25 + qq];
            ulonglong2 wA = ws[qq * 512 + j0];
            ulonglong2 wB = ws[qq * 512 + j1];
            a00 = fma2(wA.x, h2.x, a00);
            a01 = fma2(wA.y, h2.y, a01);
            a10 = fma2(wB.x, h2.x, a10);
            a11 = fma2(wB.y, h2.y, a11);
        }
        float2 s0 = upk(a00), s1 = upk(a01);
        float2 s2 = upk(a10), s3 = upk(a11);
        float z0 = (s0.x + s0.y) + (s1.x + s1.y) + zc0;
        float z1 = (s2.x + s2.y) + (s3.x + s3.y) + zc1;

        // col j0: gate 0 (i, sigm) or 1 (j, tanh); col j1: gate 2 (f, sigm+1) or 3 (o, sigm)
        float act0, act1;
        if (tid < 128) { act0 = sigm(z0);      act1 = sigm(z1 + 1.0f); }
        else           { act0 = tanh_fast(z0); act1 = sigm(z1); }
        zs[j0] = act0;
        zs[j1] = act1;
        __syncthreads();

        // c/h update replicated in threads q4 and q4+128 (identical arithmetic)
        float ai = zs[q4], aj = zs[q4 + 128], af = zs[q4 + 256], ao = zs[q4 + 384];
        c = fmaf(c, af, ai * aj);
        float h = ao * tanh_fast(c);
        if (tid < UU) {
            hbuf[tid] = h;
            *outp = h;
            outp += ostep;
        }
        __syncthreads();
    }
}

extern "C" void kernel_launch(void* const* d_in, const int* in_sizes, int n_in,
                              void* d_out, int out_size) {
    const float* x   = (const float*)d_in[0];
    const float* Wfw = (const float*)d_in[1];
    const float* bfw = (const float*)d_in[2];
    const float* Wbw = (const float*)d_in[3];
    const float* bbw = (const float*)d_in[4];
    float* out = (float*)d_out;

    const int recSmem = SMBLK * 512 * 16 + 2048 + 512;  // 59904
    cudaFuncSetAttribute(lstm_rec, cudaFuncAttributeMaxDynamicSharedMemorySize, recSmem);

    dim3 gg(4, 1024, 2);
    gemm_xw<<<gg, 256>>>(x, Wfw, bfw, Wbw, bbw);
    lstm_rec<<<128, RECTHR, recSmem>>>(Wfw, Wbw, out);
}

// round 6
// speedup vs baseline: 1.4508x; 1.2684x over previous
#include <cuda_runtime.h>
#include <cuda_bf16.h>
#include <cstdint>
#include <cstddef>

// Problem constants
#define BB 64
#define TT 2048
#define FF 128
#define UU 128
#define GG 512               // 4*U
#define MM (BB * TT)         // 131072 rows of x

// Scratch buffers (static __device__; allocation is forbidden)
__device__ float g_Z[2ull * 131072ull * 512ull];                 // z = x@Wx + b, both dirs
__device__ __align__(16) __nv_bfloat16 g_XH[131072ull * 128ull]; // x hi (bf16)
__device__ __align__(16) __nv_bfloat16 g_XL[131072ull * 128ull]; // x lo
__device__ __align__(16) __nv_bfloat16 g_WtH[2ull * 512ull * 128ull]; // W_x^T hi [dir][n][k]
__device__ __align__(16) __nv_bfloat16 g_WtL[2ull * 512ull * 128ull]; // W_x^T lo

// ---------------- f32x2 packed helpers ----------------
__device__ __forceinline__ unsigned long long fma2(unsigned long long a,
                                                   unsigned long long b,
                                                   unsigned long long c) {
    unsigned long long d;
    asm("fma.rn.f32x2 %0, %1, %2, %3;" : "=l"(d) : "l"(a), "l"(b), "l"(c));
    return d;
}
__device__ __forceinline__ unsigned long long pk(float x, float y) {
    unsigned long long d;
    asm("mov.b64 %0, {%1, %2};" : "=l"(d) : "f"(x), "f"(y));
    return d;
}
__device__ __forceinline__ float2 upk(unsigned long long a) {
    float2 r;
    asm("mov.b64 {%0, %1}, %2;" : "=f"(r.x), "=f"(r.y) : "l"(a));
    return r;
}

// ---------------- activations ----------------
__device__ __forceinline__ float sigm(float x) {
    return __fdividef(1.0f, 1.0f + __expf(-x));
}
__device__ __forceinline__ float tanh_fast(float x) {
    float ax = fabsf(x);
    float e  = __expf(-2.0f * ax);
    float r  = __fdividef(1.0f - e, 1.0f + e);
    return copysignf(r, x);
}

// ---------------- mma.sync helpers (no 'a'-target needed) ----------------
__device__ __forceinline__ uint32_t smem_u32(const void* p) {
    uint32_t a;
    asm("{ .reg .u64 t; cvta.to.shared.u64 t, %1; cvt.u32.u64 %0, t; }" : "=r"(a) : "l"(p));
    return a;
}
__device__ __forceinline__ void ldsm_x4(uint32_t addr, uint32_t* r) {
    asm volatile("ldmatrix.sync.aligned.m8n8.x4.shared.b16 {%0,%1,%2,%3}, [%4];"
                 : "=r"(r[0]), "=r"(r[1]), "=r"(r[2]), "=r"(r[3]) : "r"(addr));
}
__device__ __forceinline__ void mma_bf16(float* c, const uint32_t* a,
                                         uint32_t b0, uint32_t b1) {
    asm volatile("mma.sync.aligned.m16n8k16.row.col.f32.bf16.bf16.f32 "
                 "{%0,%1,%2,%3}, {%4,%5,%6,%7}, {%8,%9}, {%0,%1,%2,%3};"
                 : "+f"(c[0]), "+f"(c[1]), "+f"(c[2]), "+f"(c[3])
                 : "r"(a[0]), "r"(a[1]), "r"(a[2]), "r"(a[3]), "r"(b0), "r"(b1));
}

// =====================================================================
// Prep 1: x (fp32) -> XH, XL (bf16 split). 8 elems/thread.
// =====================================================================
__global__ __launch_bounds__(256) void convert_x(const float* __restrict__ x) {
    size_t i = ((size_t)blockIdx.x * 256 + threadIdx.x) * 8;
    float4 a = *(const float4*)(x + i);
    float4 b = *(const float4*)(x + i + 4);
    float f[8] = {a.x, a.y, a.z, a.w, b.x, b.y, b.z, b.w};
    union { __nv_bfloat16 h[8]; uint4 u; } H, L;
#pragma unroll
    for (int e = 0; e < 8; e++) {
        __nv_bfloat16 hi = __float2bfloat16(f[e]);
        H.h[e] = hi;
        L.h[e] = __float2bfloat16(f[e] - __bfloat162float(hi));
    }
    *(uint4*)(g_XH + i) = H.u;
    *(uint4*)(g_XL + i) = L.u;
}

// =====================================================================
// Prep 2: W_x (rows 0..127 of W) -> transposed bf16 split [dir][n][k]
// =====================================================================
__global__ __launch_bounds__(128) void transpose_w(const float* __restrict__ Wfw,
                                                   const float* __restrict__ Wbw) {
    int blk = blockIdx.x;
    int dir = blk >> 9;
    int n   = blk & 511;
    int k   = threadIdx.x;
    const float* W = dir ? Wbw : Wfw;
    float f = W[(size_t)k * GG + n];
    __nv_bfloat16 hi = __float2bfloat16(f);
    size_t o = ((size_t)dir * 512 + n) * 128 + k;
    g_WtH[o] = hi;
    g_WtL[o] = __float2bfloat16(f - __bfloat162float(hi));
}

// =====================================================================
// Phase 1: HMMA bf16-split GEMM.  Z[dir] = X @ Wx^T(dir) + bias
// CTA tile M=128, N=128, K=128 fully smem-resident (AH/AL/BH/BL = 128 KB).
// 8 warps as 4(m) x 2(n): warp tile 32x64. 3 accumulate passes.
// grid (1024, 4, 2), block 256.
// smem: AH@0 AL@32768 BH@65536 BL@98304  (each 128 rows x 256 B, swizzled)
// =====================================================================
__global__ __launch_bounds__(256) void gemm_mma(const float* __restrict__ bfw,
                                                const float* __restrict__ bbw) {
    extern __shared__ unsigned char sm[];
    const int tid = threadIdx.x;
    const int m0 = blockIdx.x * 128;
    const int n0 = blockIdx.y * 128;
    const int dir = blockIdx.z;

    // ---- gmem -> smem (swizzled: 16B unit u at row r stored at u' = (u&8)|((u^r)&7)) ----
#pragma unroll
    for (int buf = 0; buf < 2; buf++) {
        const __nv_bfloat16* A = buf ? g_XL : g_XH;
#pragma unroll
        for (int it = 0; it < 8; it++) {
            int task = it * 256 + tid;
            int r = task >> 4, u = task & 15;
            uint4 v = *(const uint4*)(A + (size_t)(m0 + r) * 128 + u * 8);
            int up = (u & 8) | ((u ^ r) & 7);
            *(uint4*)(sm + buf * 32768 + r * 256 + up * 16) = v;
        }
        const __nv_bfloat16* Bw = (buf ? g_WtL : g_WtH) + ((size_t)dir * 512 + n0) * 128;
#pragma unroll
        for (int it = 0; it < 8; it++) {
            int task = it * 256 + tid;
            int r = task >> 4, u = task & 15;
            uint4 v = *(const uint4*)(Bw + (size_t)r * 128 + u * 8);
            int up = (u & 8) | ((u ^ r) & 7);
            *(uint4*)(sm + 65536 + buf * 32768 + r * 256 + up * 16) = v;
        }
    }
    __syncthreads();

    const int w = tid >> 5, l = tid & 31;
    const int mb = (w & 3) * 32;     // warp m offset in tile
    const int nb = (w >> 2) * 64;    // warp n offset in tile
    const uint32_t sbase = smem_u32(sm);

    float c[2][8][4];
#pragma unroll
    for (int mi = 0; mi < 2; mi++)
#pragma unroll
        for (int ni = 0; ni < 8; ni++)
#pragma unroll
            for (int q = 0; q < 4; q++) c[mi][ni][q] = 0.0f;

    // per-lane ldmatrix row/unit components
    const int rAl = mb + (l & 15);           // A row (within 128), + mi*16
    const int hA  = l >> 4;                  // A k-unit half
    const int rBl = nb + (l & 7) + ((l >> 4) << 3);  // B row, + ni2*16
    const int hB  = (l >> 3) & 1;            // B k-unit half

#pragma unroll
    for (int p = 0; p < 3; p++) {
        const uint32_t Ab = sbase + (p == 2 ? 32768u : 0u);
        const uint32_t Bb = sbase + 65536u + (p == 1 ? 32768u : 0u);
#pragma unroll
        for (int kc = 0; kc < 8; kc++) {
            uint32_t a[2][4];
#pragma unroll
            for (int mi = 0; mi < 2; mi++) {
                int row = rAl + mi * 16;
                int u = kc * 2 + hA;
                uint32_t addr = Ab + row * 256 + ((u & 8) | ((u ^ row) & 7)) * 16;
                ldsm_x4(addr, a[mi]);
            }
            uint32_t b[4][4];
#pragma unroll
            for (int ni2 = 0; ni2 < 4; ni2++) {
                int row = rBl + ni2 * 16;
                int u = kc * 2 + hB;
                uint32_t addr = Bb + row * 256 + ((u & 8) | ((u ^ row) & 7)) * 16;
                ldsm_x4(addr, b[ni2]);
            }
#pragma unroll
            for (int mi = 0; mi < 2; mi++)
#pragma unroll
                for (int ni = 0; ni < 8; ni++)
                    mma_bf16(c[mi][ni], a[mi], b[ni >> 1][(ni & 1) * 2],
                             b[ni >> 1][(ni & 1) * 2 + 1]);
        }
    }

    // ---- epilogue: bias + direct float2 stores (sector-packed) ----
    const float* bias = dir ? bbw : bfw;
    const int gcol0 = n0 + nb + (l & 3) * 2;
    float2 bs[8];
#pragma unroll
    for (int ni = 0; ni < 8; ni++) bs[ni] = *(const float2*)(bias + gcol0 + ni * 8);

    float* Zb = g_Z + (size_t)dir * ((size_t)MM * GG);
    const int grow0 = m0 + mb + (l >> 2);
#pragma unroll
    for (int mi = 0; mi < 2; mi++) {
        float* r0 = Zb + (size_t)(grow0 + mi * 16) * GG;
        float* r1 = r0 + (size_t)8 * GG;
#pragma unroll
        for (int ni = 0; ni < 8; ni++) {
            float2 v0 = make_float2(c[mi][ni][0] + bs[ni].x, c[mi][ni][1] + bs[ni].y);
            float2 v1 = make_float2(c[mi][ni][2] + bs[ni].x, c[mi][ni][3] + bs[ni].y);
            *(float2*)(r0 + gcol0 + ni * 8) = v0;
            *(float2*)(r1 + gcol0 + ni * 8) = v1;
        }
    }
}

// =====================================================================
// Phase 2: persistent recurrence (unchanged from R2; 1.525 ms measured).
// =====================================================================
#define RECTHR 256
#define SMBLK  7
#define RPAIR  50

__global__ __launch_bounds__(RECTHR) void lstm_rec(
    const float* __restrict__ Wfw,
    const float* __restrict__ Wbw,
    float* __restrict__ out) {
    const int tid = threadIdx.x;
    const int j0  = tid;
    const int j1  = tid + 256;
    const int dir = blockIdx.x & 1;
    const int b   = blockIdx.x >> 1;
    const float* W  = dir ? Wbw : Wfw;
    const float* Wh = W + FF * GG;

    extern __shared__ unsigned char sraw[];
    ulonglong2* ws = (ulonglong2*)sraw;
    float* zs   = (float*)(sraw + SMBLK * 512 * 16);
    float* hbuf = (float*)(sraw + SMBLK * 512 * 16 + 2048);

    unsigned long long w0[2 * RPAIR];
    unsigned long long w1[2 * RPAIR];
#pragma unroll
    for (int p = 0; p < RPAIR; p++) {
        w0[p] = pk(Wh[(size_t)(2 * p) * GG + j0], Wh[(size_t)(2 * p + 1) * GG + j0]);
        w1[p] = pk(Wh[(size_t)(2 * p) * GG + j1], Wh[(size_t)(2 * p + 1) * GG + j1]);
    }
#pragma unroll
    for (int q = 0; q < SMBLK; q++) {
        int r = 100 + 4 * q;
        ulonglong2 vA, vB;
        vA.x = pk(Wh[(size_t)(r + 0) * GG + j0], Wh[(size_t)(r + 1) * GG + j0]);
        vA.y = pk(Wh[(size_t)(r + 2) * GG + j0], Wh[(size_t)(r + 3) * GG + j0]);
        vB.x = pk(Wh[(size_t)(r + 0) * GG + j1], Wh[(size_t)(r + 1) * GG + j1]);
        vB.y = pk(Wh[(size_t)(r + 2) * GG + j1], Wh[(size_t)(r + 3) * GG + j1]);
        ws[q * 512 + j0] = vA;
        ws[q * 512 + j1] = vB;
    }
    if (tid < UU) hbuf[tid] = 0.0f;
    float c = 0.0f;
    __syncthreads();

    const size_t base = ((size_t)dir * MM + (size_t)b * TT) * GG;
    const float* zp;
    long long zstep;
    int tt0;
    if (dir == 0) { zp = g_Z + base;                          zstep =  GG; tt0 = 0; }
    else          { zp = g_Z + base + (size_t)(TT - 1) * GG;  zstep = -GG; tt0 = TT - 1; }
    float zn0 = zp[j0], zn1 = zp[j1];

    float* outp = out + ((size_t)b * TT + tt0) * (2 * UU) + dir * UU + tid;
    const long long ostep = (dir == 0) ? (2 * UU) : -(2 * UU);
    const int q4 = tid & 127;

    for (int t = 0; t < TT; t++) {
        float zc0 = zn0, zc1 = zn1;
        if (t + 1 < TT) { zp += zstep; zn0 = zp[j0]; zn1 = zp[j1]; }

        const ulonglong2* hb = (const ulonglong2*)hbuf;
        unsigned long long a00 = 0ull, a01 = 0ull, a10 = 0ull, a11 = 0ull;
#pragma unroll
        for (int p = 0; p < 25; p++) {
            ulonglong2 h2 = hb[p];
            a00 = fma2(w0[2 * p], h2.x, a00);
            a01 = fma2(w0[2 * p + 1], h2.y, a01);
            a10 = fma2(w1[2 * p], h2.x, a10);
            a11 = fma2(w1[2 * p + 1], h2.y, a11);
        }
#pragma unroll
        for (int qq = 0; qq < SMBLK; qq++) {
            ulonglong2 h2 = hb[25 + qq];
            ulonglong2 wA = ws[qq * 512 + j0];
            ulonglong2 wB = ws[qq * 512 + j1];
            a00 = fma2(wA.x, h2.x, a00);
            a01 = fma2(wA.y, h2.y, a01);
            a10 = fma2(wB.x, h2.x, a10);
            a11 = fma2(wB.y, h2.y, a11);
        }
        float2 s0 = upk(a00), s1 = upk(a01);
        float2 s2 = upk(a10), s3 = upk(a11);
        float z0 = (s0.x + s0.y) + (s1.x + s1.y) + zc0;
        float z1 = (s2.x + s2.y) + (s3.x + s3.y) + zc1;

        float act0, act1;
        if (tid < 128) { act0 = sigm(z0);      act1 = sigm(z1 + 1.0f); }
        else           { act0 = tanh_fast(z0); act1 = sigm(z1); }
        zs[j0] = act0;
        zs[j1] = act1;
        __syncthreads();

        float ai = zs[q4], aj = zs[q4 + 128], af = zs[q4 + 256], ao = zs[q4 + 384];
        c = fmaf(c, af, ai * aj);
        float h = ao * tanh_fast(c);
        if (tid < UU) {
            hbuf[tid] = h;
            *outp = h;
            outp += ostep;
        }
        __syncthreads();
    }
}

extern "C" void kernel_launch(void* const* d_in, const int* in_sizes, int n_in,
                              void* d_out, int out_size) {
    const float* x   = (const float*)d_in[0];
    const float* Wfw = (const float*)d_in[1];
    const float* bfw = (const float*)d_in[2];
    const float* Wbw = (const float*)d_in[3];
    const float* bbw = (const float*)d_in[4];
    float* out = (float*)d_out;

    cudaFuncSetAttribute(gemm_mma, cudaFuncAttributeMaxDynamicSharedMemorySize, 131072);
    const int recSmem = SMBLK * 512 * 16 + 2048 + 512;  // 59904
    cudaFuncSetAttribute(lstm_rec, cudaFuncAttributeMaxDynamicSharedMemorySize, recSmem);

    convert_x<<<8192, 256>>>(x);
    transpose_w<<<1024, 128>>>(Wfw, Wbw);
    dim3 gg(1024, 4, 2);
    gemm_mma<<<gg, 256, 131072>>>(bfw, bbw);
    lstm_rec<<<128, RECTHR, recSmem>>>(Wfw, Wbw, out);
}